// round 16
// baseline (speedup 1.0000x reference)
#include <cuda_runtime.h>
#include <cuda_fp16.h>
#include <cstdint>

#define BDIM 8
#define NDIM 256
#define HDIM 128
#define INDIM 259
#define NODES (BDIM * NDIM)   // 2048

// ---------------- device scratch ----------------
__device__ float g_P[NODES * HDIM];
__device__ __half g_Qh[NODES * HDIM];
__device__ float g_b1eff[HDIM];
__device__ __half g_Wfh[HDIM * HDIM];               // W1c@Wd [h][k], f16
__device__ __half g_W2h[HDIM * HDIM];               // W2 [g][h], f16
__device__ float g_W1aT[HDIM * HDIM];
__device__ float g_W1bT[HDIM * HDIM];
__device__ float g_part[NODES * 16 * 3];            // per (blk, warp) partials

// ---------------- helpers ----------------
__device__ __forceinline__ unsigned pack_h2(float lo, float hi) {
    unsigned r;
    asm("cvt.rn.f16x2.f32 %0, %1, %2;" : "=r"(r) : "f"(hi), "f"(lo));
    return r;
}
__device__ __forceinline__ unsigned silu2(float x0, float x1) {
    unsigned hx = pack_h2(x0, x1), hh, th, res;
    asm("mul.rn.f16x2 %0, %1, %2;" : "=r"(hh) : "r"(hx), "r"(0x38003800u));
    asm("tanh.approx.f16x2 %0, %1;" : "=r"(th) : "r"(hh));
    asm("fma.rn.f16x2 %0, %1, %2, %3;" : "=r"(res) : "r"(hh), "r"(th), "r"(hh));
    return res;
}
__device__ __forceinline__ uint32_t smem_u32(const void* p) {
    uint32_t a;
    asm("{ .reg .u64 t; cvta.to.shared.u64 t, %1; cvt.u32.u64 %0, t; }" : "=r"(a) : "l"(p));
    return a;
}

#define CP16(dst, src) \
    asm volatile("cp.async.cg.shared.global [%0], [%1], 16;" :: "r"(dst), "l"(src))
#define CP_COMMIT() asm volatile("cp.async.commit_group;")
#define CP_WAIT0()  asm volatile("cp.async.wait_group 0;")

// ---------------- prep_w ----------------
__global__ __launch_bounds__(256)
void prep_w(const float* __restrict__ Wd, const float* __restrict__ bd,
            const float* __restrict__ W1, const float* __restrict__ b1,
            const float* __restrict__ W2) {
    int h = blockIdx.x;
    int t = threadIdx.x;
    if (t < 128) {
        int k = t;
        float w1c0 = W1[h * INDIM + 2 * HDIM + 0];
        float w1c1 = W1[h * INDIM + 2 * HDIM + 1];
        float w1c2 = W1[h * INDIM + 2 * HDIM + 2];
        float v = w1c0 * Wd[k] + w1c1 * Wd[HDIM + k] + w1c2 * Wd[2 * HDIM + k];
        g_Wfh[h * HDIM + k] = __float2half_rn(v);
        g_W2h[h * HDIM + k] = __float2half_rn(W2[h * HDIM + k]);
        g_W1aT[k * HDIM + h] = W1[h * INDIM + k];
        if (k == 0)
            g_b1eff[h] = b1[h] + w1c0 * bd[0] + w1c1 * bd[1] + w1c2 * bd[2];
    } else {
        int k = t - 128;
        g_W1bT[k * HDIM + h] = W1[h * INDIM + HDIM + k];
    }
}

// ---------------- prep_pq ----------------
__global__ __launch_bounds__(256)
void prep_pq(const float* __restrict__ x_emb) {
    __shared__ float xs[8][HDIM];
    int t = threadIdx.x;
    int r0 = blockIdx.x * 8;
    for (int idx = t; idx < 8 * HDIM; idx += 256)
        xs[idx >> 7][idx & 127] = x_emb[r0 * HDIM + idx];
    __syncthreads();

    const int h = t & 127;
    const int n0 = (t >> 7) * 4;

    float p[4] = {0.f, 0.f, 0.f, 0.f};
    float q[4] = {0.f, 0.f, 0.f, 0.f};
#pragma unroll 4
    for (int k = 0; k < HDIM; k++) {
        float wa = g_W1aT[k * HDIM + h];
        float wb = g_W1bT[k * HDIM + h];
#pragma unroll
        for (int ii = 0; ii < 4; ii++) {
            float xv = xs[n0 + ii][k];
            p[ii] = fmaf(wa, xv, p[ii]);
            q[ii] = fmaf(wb, xv, q[ii]);
        }
    }
#pragma unroll
    for (int ii = 0; ii < 4; ii++) {
        g_P[(size_t)(r0 + n0 + ii) * HDIM + h]  = p[ii];
        g_Qh[(size_t)(r0 + n0 + ii) * HDIM + h] = __float2half_rn(q[ii]);
    }
}

// ---------------- main: one CTA per (b,i); warp-independent pipeline ----------------
// 16 warps x 16 rows = 256 j-rows. Each warp: load A rows -> GEMM1 (all 128 cols,
// 8 col-chunks) -> silu to register f16 fragments (D-layout == A-layout identity)
// -> GEMM2 (A from registers, 4 col-chunks) -> dot W3 -> warp partial.
// NO intra-tile barriers; one __syncthreads after weight staging.

#define PA 136                 // smem pitch in f16
#define ROWB (PA * 2)          // 272 B

#define OFF_A     0            // 256*272 = 69632
#define OFF_B1    69632        // 34816 (Wfuse f16)
#define OFF_B2    104448       // 34816 (W2 f16)
#define OFF_BIAS  139264       // float[128]  P[blk] + b1eff
#define OFF_W3    139776       // float[128]
#define OFF_B2V   140288       // float[128]
#define SMEM_TOTAL 140800

#define LDSM_X4(r0, r1, r2, r3, addr) \
    asm volatile("ldmatrix.sync.aligned.m8n8.x4.shared.b16 {%0,%1,%2,%3}, [%4];" \
                 : "=r"(r0), "=r"(r1), "=r"(r2), "=r"(r3) : "r"(addr))

#define MMA_F16(d0, d1, d2, d3, a0, a1, a2, a3, b0, b1) \
    asm volatile("mma.sync.aligned.m16n8k16.row.col.f32.f16.f16.f32 " \
                 "{%0,%1,%2,%3}, {%4,%5,%6,%7}, {%8,%9}, {%0,%1,%2,%3};\n" \
                 : "+f"(d0), "+f"(d1), "+f"(d2), "+f"(d3) \
                 : "r"(a0), "r"(a1), "r"(a2), "r"(a3), "r"(b0), "r"(b1))

__global__ __launch_bounds__(512, 1)
void pos_update_main(const float* __restrict__ pair_emb,
                     const float* __restrict__ coord_diff,
                     const float* __restrict__ pair_mask,
                     const float* __restrict__ b2,
                     const float* __restrict__ W3) {
    extern __shared__ char smem[];
    __half* As   = reinterpret_cast<__half*>(smem + OFF_A);
    float* biasI = reinterpret_cast<float*>(smem + OFF_BIAS);
    float* w3s   = reinterpret_cast<float*>(smem + OFF_W3);
    float* b2s   = reinterpret_cast<float*>(smem + OFF_B2V);

    const uint32_t sb = smem_u32(smem);
    const int tid  = threadIdx.x;
    const int lane = tid & 31;
    const int warp = tid >> 5;
    const int g = lane >> 2, l4 = lane & 3;
    const int blk = blockIdx.x;               // b*256 + i
    const int bbase = blk & ~255;             // b*256
    const int r0 = warp * 16;                 // this warp's 16 j-rows

    const uint32_t aLane = sb + OFF_A + (uint32_t)(r0 + (lane & 15)) * ROWB
                              + (uint32_t)(lane >> 4) * 16;
    const uint32_t bPat  = (uint32_t)((lane & 7) + ((lane >> 4) << 3)) * ROWB
                              + (uint32_t)((lane >> 3) & 1) * 16;
    const uint32_t bBase1 = sb + OFF_B1 + bPat;
    const uint32_t bBase2 = sb + OFF_B2 + bPat;

    // ---- per-CTA setup: weights via cp.async, bias/W3/b2 staging ----
    {
        const char* w1 = reinterpret_cast<const char*>(g_Wfh);
        const char* w2 = reinterpret_cast<const char*>(g_W2h);
#pragma unroll
        for (int it = 0; it < 4; it++) {
            int idx = tid + it * 512;         // 2048 x 16B
            int r = idx >> 4, c = (idx & 15) << 3;
            uint32_t doff = (uint32_t)(r * PA + c) * 2;
            CP16(sb + OFF_B1 + doff, w1 + idx * 16);
            CP16(sb + OFF_B2 + doff, w2 + idx * 16);
        }
        CP_COMMIT();
        if (tid < 128) {
            biasI[tid] = g_P[(size_t)blk * HDIM + tid] + g_b1eff[tid];
            w3s[tid] = W3[tid];
            b2s[tid] = b2[tid];
        }
        CP_WAIT0();
    }
    __syncthreads();   // only CTA-wide barrier

    // ---- load this warp's 16 A rows (fp32 -> f16 smem) ----
    {
        const float4* src = reinterpret_cast<const float4*>(
            pair_emb + ((size_t)blk * NDIM + r0) * HDIM);
#pragma unroll
        for (int i = 0; i < 16; i++) {
            int idx = lane + i * 32;          // 512 float4 per warp
            float4 f = src[idx];
            int row = idx >> 5;               // 0..15
            int c = (idx & 31) << 2;
            uint2 v;
            v.x = pack_h2(f.x, f.y);
            v.y = pack_h2(f.z, f.w);
            *reinterpret_cast<uint2*>(As + (r0 + row) * PA + c) = v;
        }
        __syncwarp();
    }

    // ---- A fragments (8 ksteps x 4 regs) ----
    uint32_t areg[8][4];
#pragma unroll
    for (int ks = 0; ks < 8; ks++)
        LDSM_X4(areg[ks][0], areg[ks][1], areg[ks][2], areg[ks][3],
                aLane + ks * 32);

    const int rg  = r0 + g;       // this thread's row (and rg+8)
    const __half* qra = g_Qh + (size_t)(bbase + rg) * HDIM;
    const __half* qrb = qra + 8 * HDIM;

    // ---- GEMM1: 8 chunks of 16 columns; silu -> register H1 fragments ----
    unsigned h1f[8][4];
#pragma unroll
    for (int nc = 0; nc < 8; nc++) {
        float acc[8] = {0.f, 0.f, 0.f, 0.f, 0.f, 0.f, 0.f, 0.f};
        uint32_t bb[4];
#pragma unroll
        for (int ks = 0; ks < 8; ks++) {
            LDSM_X4(bb[0], bb[1], bb[2], bb[3],
                    bBase1 + nc * (16 * ROWB) + ks * 32);
            MMA_F16(acc[0], acc[1], acc[2], acc[3],
                    areg[ks][0], areg[ks][1], areg[ks][2], areg[ks][3],
                    bb[0], bb[1]);
            MMA_F16(acc[4], acc[5], acc[6], acc[7],
                    areg[ks][0], areg[ks][1], areg[ks][2], areg[ks][3],
                    bb[2], bb[3]);
        }
        int ca = nc * 16 + 2 * l4;            // cols for nt=2nc
        int cb = ca + 8;                      // cols for nt=2nc+1
        float pa0 = biasI[ca], pa1 = biasI[ca + 1];
        float pb0 = biasI[cb], pb1 = biasI[cb + 1];
        float2 qa0 = __half22float2(*reinterpret_cast<const __half2*>(qra + ca));
        float2 qa8 = __half22float2(*reinterpret_cast<const __half2*>(qrb + ca));
        float2 qb0 = __half22float2(*reinterpret_cast<const __half2*>(qra + cb));
        float2 qb8 = __half22float2(*reinterpret_cast<const __half2*>(qrb + cb));
        // D-layout == next A-fragment layout (per-thread identity):
        h1f[nc][0] = silu2(acc[0] + pa0 + qa0.x, acc[1] + pa1 + qa0.y); // row g,   k lo
        h1f[nc][1] = silu2(acc[2] + pa0 + qa8.x, acc[3] + pa1 + qa8.y); // row g+8, k lo
        h1f[nc][2] = silu2(acc[4] + pb0 + qb0.x, acc[5] + pb1 + qb0.y); // row g,   k hi
        h1f[nc][3] = silu2(acc[6] + pb0 + qb8.x, acc[7] + pb1 + qb8.y); // row g+8, k hi
    }

    // ---- GEMM2: 4 chunks of 32 columns; A fragments straight from h1f ----
    float s0 = 0.f, s1 = 0.f;
#pragma unroll
    for (int mc = 0; mc < 4; mc++) {
        float acc[16];
#pragma unroll
        for (int e = 0; e < 16; e++) acc[e] = 0.f;
#pragma unroll
        for (int ks = 0; ks < 8; ks++) {
            uint32_t b0[4], b1r[4];
            LDSM_X4(b0[0], b0[1], b0[2], b0[3],
                    bBase2 + (2 * mc) * (16 * ROWB) + ks * 32);
            LDSM_X4(b1r[0], b1r[1], b1r[2], b1r[3],
                    bBase2 + (2 * mc + 1) * (16 * ROWB) + ks * 32);
            MMA_F16(acc[0], acc[1], acc[2], acc[3],
                    h1f[ks][0], h1f[ks][1], h1f[ks][2], h1f[ks][3], b0[0], b0[1]);
            MMA_F16(acc[4], acc[5], acc[6], acc[7],
                    h1f[ks][0], h1f[ks][1], h1f[ks][2], h1f[ks][3], b0[2], b0[3]);
            MMA_F16(acc[8], acc[9], acc[10], acc[11],
                    h1f[ks][0], h1f[ks][1], h1f[ks][2], h1f[ks][3], b1r[0], b1r[1]);
            MMA_F16(acc[12], acc[13], acc[14], acc[15],
                    h1f[ks][0], h1f[ks][1], h1f[ks][2], h1f[ks][3], b1r[2], b1r[3]);
        }
#pragma unroll
        for (int ntl = 0; ntl < 4; ntl++) {
            int c = (4 * mc + ntl) * 8 + 2 * l4;
            float bb0 = b2s[c], bb1 = b2s[c + 1];
            float w30 = w3s[c], w31 = w3s[c + 1];
            unsigned ylo = silu2(acc[ntl * 4 + 0] + bb0, acc[ntl * 4 + 1] + bb1);
            unsigned yhi = silu2(acc[ntl * 4 + 2] + bb0, acc[ntl * 4 + 3] + bb1);
            float2 y01 = __half22float2(*reinterpret_cast<__half2*>(&ylo));
            float2 y23 = __half22float2(*reinterpret_cast<__half2*>(&yhi));
            s0 += y01.x * w30 + y01.y * w31;   // row g
            s1 += y23.x * w30 + y23.y * w31;   // row g+8
        }
    }

    // ---- reduce over l4 -> s[j] for rows rg, rg+8 ----
    s0 += __shfl_xor_sync(0xffffffffu, s0, 1);
    s0 += __shfl_xor_sync(0xffffffffu, s0, 2);
    s1 += __shfl_xor_sync(0xffffffffu, s1, 1);
    s1 += __shfl_xor_sync(0xffffffffu, s1, 2);

    float t0 = 0.f, t1 = 0.f, t2 = 0.f;
    if (l4 == 0) {
        size_t ja = (size_t)blk * NDIM + rg;
        size_t jb = ja + 8;
        float sj0 = s0 * pair_mask[ja];
        float sj1 = s1 * pair_mask[jb];
        const float* cda = coord_diff + ja * 3;
        const float* cdb = coord_diff + jb * 3;
        t0 = cda[0] * sj0 + cdb[0] * sj1;
        t1 = cda[1] * sj0 + cdb[1] * sj1;
        t2 = cda[2] * sj0 + cdb[2] * sj1;
    }
#pragma unroll
    for (int off = 4; off <= 16; off <<= 1) {
        t0 += __shfl_xor_sync(0xffffffffu, t0, off);
        t1 += __shfl_xor_sync(0xffffffffu, t1, off);
        t2 += __shfl_xor_sync(0xffffffffu, t2, off);
    }
    if (lane == 0) {
        float* gp = g_part + ((size_t)blk * 16 + warp) * 3;
        gp[0] = t0; gp[1] = t1; gp[2] = t2;
    }
}

// ---------------- combine kernel ----------------
__global__ void combine(const float* __restrict__ pos, float* __restrict__ out) {
    int i = blockIdx.x * blockDim.x + threadIdx.x;   // 0..6143
    if (i < NODES * 3) {
        int node = i / 3, d = i - node * 3;
        const float* gp = g_part + (size_t)node * 16 * 3 + d;
        float s = 0.f;
#pragma unroll
        for (int w = 0; w < 16; w++) s += gp[w * 3];
        out[i] = pos[i] + s;
    }
}

// ---------------- launcher ----------------
extern "C" void kernel_launch(void* const* d_in, const int* in_sizes, int n_in,
                              void* d_out, int out_size) {
    const float* x_emb      = (const float*)d_in[0];
    const float* pair_emb   = (const float*)d_in[1];
    const float* pos        = (const float*)d_in[2];
    const float* coord_diff = (const float*)d_in[3];
    const float* pair_mask  = (const float*)d_in[5];
    const float* Wd         = (const float*)d_in[6];
    const float* bd         = (const float*)d_in[7];
    const float* W1         = (const float*)d_in[8];
    const float* b1         = (const float*)d_in[9];
    const float* W2         = (const float*)d_in[10];
    const float* b2         = (const float*)d_in[11];
    const float* W3         = (const float*)d_in[12];
    float* out = (float*)d_out;

    cudaFuncSetAttribute(pos_update_main,
                         cudaFuncAttributeMaxDynamicSharedMemorySize, SMEM_TOTAL);

    prep_w<<<128, 256>>>(Wd, bd, W1, b1, W2);
    prep_pq<<<256, 256>>>(x_emb);
    pos_update_main<<<NODES, 512, SMEM_TOTAL>>>(pair_emb, coord_diff,
                                                pair_mask, b2, W3);
    combine<<<(NODES * 3 + 511) / 512, 512>>>(pos, out);
    (void)in_sizes; (void)n_in; (void)out_size;
}

// round 17
// speedup vs baseline: 1.0456x; 1.0456x over previous
#include <cuda_runtime.h>
#include <cuda_fp16.h>
#include <cstdint>

#define BDIM 8
#define NDIM 256
#define HDIM 128
#define INDIM 259
#define NODES (BDIM * NDIM)   // 2048
#define NTILES (2 * NODES)    // 4096

// ---------------- device scratch ----------------
__device__ float g_P[NODES * HDIM];
__device__ __half g_Qh[NODES * HDIM];
__device__ float g_b1eff[HDIM];
__device__ __half g_Wfh[HDIM * HDIM];               // W1c@Wd [h][k], f16
__device__ __half g_W2h[HDIM * HDIM];               // W2 [g][h], f16
__device__ float g_W1aT[HDIM * HDIM];
__device__ float g_W1bT[HDIM * HDIM];
__device__ float g_part[NTILES * 2 * 3];            // per (tile, wm) partials

// ---------------- helpers ----------------
__device__ __forceinline__ unsigned pack_h2(float lo, float hi) {
    unsigned r;
    asm("cvt.rn.f16x2.f32 %0, %1, %2;" : "=r"(r) : "f"(hi), "f"(lo));
    return r;
}
__device__ __forceinline__ unsigned silu2(float x0, float x1) {
    unsigned hx = pack_h2(x0, x1), hh, th, res;
    asm("mul.rn.f16x2 %0, %1, %2;" : "=r"(hh) : "r"(hx), "r"(0x38003800u));
    asm("tanh.approx.f16x2 %0, %1;" : "=r"(th) : "r"(hh));
    asm("fma.rn.f16x2 %0, %1, %2, %3;" : "=r"(res) : "r"(hh), "r"(th), "r"(hh));
    return res;
}
__device__ __forceinline__ uint32_t smem_u32(const void* p) {
    uint32_t a;
    asm("{ .reg .u64 t; cvta.to.shared.u64 t, %1; cvt.u32.u64 %0, t; }" : "=r"(a) : "l"(p));
    return a;
}

#define CP16(dst, src) \
    asm volatile("cp.async.cg.shared.global [%0], [%1], 16;" :: "r"(dst), "l"(src))
#define CP_COMMIT() asm volatile("cp.async.commit_group;")
#define CP_WAIT0()  asm volatile("cp.async.wait_group 0;")
// wm-group barrier: 2 warps = 64 threads
#define BAR_GROUP(id) \
    asm volatile("bar.sync %0, 64;" :: "r"(id) : "memory")

// ---------------- prep_w ----------------
__global__ __launch_bounds__(256)
void prep_w(const float* __restrict__ Wd, const float* __restrict__ bd,
            const float* __restrict__ W1, const float* __restrict__ b1,
            const float* __restrict__ W2) {
    int h = blockIdx.x;
    int t = threadIdx.x;
    if (t < 128) {
        int k = t;
        float w1c0 = W1[h * INDIM + 2 * HDIM + 0];
        float w1c1 = W1[h * INDIM + 2 * HDIM + 1];
        float w1c2 = W1[h * INDIM + 2 * HDIM + 2];
        float v = w1c0 * Wd[k] + w1c1 * Wd[HDIM + k] + w1c2 * Wd[2 * HDIM + k];
        g_Wfh[h * HDIM + k] = __float2half_rn(v);
        g_W2h[h * HDIM + k] = __float2half_rn(W2[h * HDIM + k]);
        g_W1aT[k * HDIM + h] = W1[h * INDIM + k];
        if (k == 0)
            g_b1eff[h] = b1[h] + w1c0 * bd[0] + w1c1 * bd[1] + w1c2 * bd[2];
    } else {
        int k = t - 128;
        g_W1bT[k * HDIM + h] = W1[h * INDIM + HDIM + k];
    }
}

// ---------------- prep_pq ----------------
__global__ __launch_bounds__(256)
void prep_pq(const float* __restrict__ x_emb) {
    __shared__ float xs[8][HDIM];
    int t = threadIdx.x;
    int r0 = blockIdx.x * 8;
    for (int idx = t; idx < 8 * HDIM; idx += 256)
        xs[idx >> 7][idx & 127] = x_emb[r0 * HDIM + idx];
    __syncthreads();

    const int h = t & 127;
    const int n0 = (t >> 7) * 4;

    float p[4] = {0.f, 0.f, 0.f, 0.f};
    float q[4] = {0.f, 0.f, 0.f, 0.f};
#pragma unroll 4
    for (int k = 0; k < HDIM; k++) {
        float wa = g_W1aT[k * HDIM + h];
        float wb = g_W1bT[k * HDIM + h];
#pragma unroll
        for (int ii = 0; ii < 4; ii++) {
            float xv = xs[n0 + ii][k];
            p[ii] = fmaf(wa, xv, p[ii]);
            q[ii] = fmaf(wb, xv, q[ii]);
        }
    }
#pragma unroll
    for (int ii = 0; ii < 4; ii++) {
        g_P[(size_t)(r0 + n0 + ii) * HDIM + h]  = p[ii];
        g_Qh[(size_t)(r0 + n0 + ii) * HDIM + h] = __float2half_rn(q[ii]);
    }
}

// ---------------- main: 64x64 warp tiles, halved LDSM traffic ----------------
// grid 4096 (one CTA per (b,i,half)), 128 threads = 4 warps in 2(wm) x 2(wn).
// Each warp: 64 rows x 64 cols. A read x2, B read x2 (vs x4/x4 in 4x4 grid).

#define PA 136                 // smem pitch in f16
#define ROWB (PA * 2)          // 272 B

#define OFF_A     0            // 128*272 = 34816 (A, reused for H1)
#define OFF_B1    34816        // 34816 (Wfuse f16)
#define OFF_B2    69632        // 34816 (W2 f16)
#define OFF_BIAS  104448       // float[128]
#define OFF_W3    104960       // float[128]
#define OFF_B2V   105472       // float[128]
#define OFF_SRED  105984       // float[2][128]
#define SMEM_TOTAL 107008

#define LDSM_X4(r0, r1, r2, r3, addr) \
    asm volatile("ldmatrix.sync.aligned.m8n8.x4.shared.b16 {%0,%1,%2,%3}, [%4];" \
                 : "=r"(r0), "=r"(r1), "=r"(r2), "=r"(r3) : "r"(addr))

#define MMA_F16(d0, d1, d2, d3, a0, a1, a2, a3, b0, b1) \
    asm volatile("mma.sync.aligned.m16n8k16.row.col.f32.f16.f16.f32 " \
                 "{%0,%1,%2,%3}, {%4,%5,%6,%7}, {%8,%9}, {%0,%1,%2,%3};\n" \
                 : "+f"(d0), "+f"(d1), "+f"(d2), "+f"(d3) \
                 : "r"(a0), "r"(a1), "r"(a2), "r"(a3), "r"(b0), "r"(b1))

// 64x64 warp-tile GEMM: acc[4][8][4], per kstep 4 A-LDSM + 4 B-LDSM, 32 MMAs
__device__ __forceinline__ void do_gemm(uint32_t aLane, uint32_t bLane,
                                        float (*acc)[8][4]) {
#pragma unroll
    for (int ks = 0; ks < 8; ks++) {
        uint32_t a[4][4], b[8][2];
#pragma unroll
        for (int mt = 0; mt < 4; mt++)
            LDSM_X4(a[mt][0], a[mt][1], a[mt][2], a[mt][3],
                    aLane + mt * (16 * ROWB) + ks * 32);
#pragma unroll
        for (int np = 0; np < 4; np++)
            LDSM_X4(b[2 * np][0], b[2 * np][1], b[2 * np + 1][0], b[2 * np + 1][1],
                    bLane + np * (16 * ROWB) + ks * 32);
#pragma unroll
        for (int mt = 0; mt < 4; mt++)
#pragma unroll
            for (int nt = 0; nt < 8; nt++)
                MMA_F16(acc[mt][nt][0], acc[mt][nt][1], acc[mt][nt][2], acc[mt][nt][3],
                        a[mt][0], a[mt][1], a[mt][2], a[mt][3],
                        b[nt][0], b[nt][1]);
    }
}

__global__ __launch_bounds__(128, 2)
void pos_update_main(const float* __restrict__ pair_emb,
                     const float* __restrict__ coord_diff,
                     const float* __restrict__ pair_mask,
                     const float* __restrict__ b2,
                     const float* __restrict__ W3) {
    extern __shared__ char smem[];
    __half* As   = reinterpret_cast<__half*>(smem + OFF_A);
    float* biasI = reinterpret_cast<float*>(smem + OFF_BIAS);
    float* w3s   = reinterpret_cast<float*>(smem + OFF_W3);
    float* b2s   = reinterpret_cast<float*>(smem + OFF_B2V);
    float* sRedW = reinterpret_cast<float*>(smem + OFF_SRED);   // [2][128]

    const uint32_t sb = smem_u32(smem);
    const int tid  = threadIdx.x;
    const int lane = tid & 31;
    const int warp = tid >> 5;
    const int wm = warp >> 1, wn = warp & 1;
    const int g = lane >> 2, l4 = lane & 3;
    const int blk2 = blockIdx.x;              // (b*256+i)*2 + half
    const int blk  = blk2 >> 1;
    const int j0   = (blk2 & 1) << 7;
    const int bbase = blk & ~255;

    const uint32_t aLane = sb + OFF_A + (uint32_t)(wm * 64 + (lane & 15)) * ROWB
                              + (uint32_t)(lane >> 4) * 16;
    const uint32_t bPat  = (uint32_t)(wn * 64 + (lane & 7) + ((lane >> 4) << 3)) * ROWB
                              + (uint32_t)((lane >> 3) & 1) * 16;
    const uint32_t bLane1 = sb + OFF_B1 + bPat;
    const uint32_t bLane2 = sb + OFF_B2 + bPat;

    // ---- load phase ----
    {
        const char* w1 = reinterpret_cast<const char*>(g_Wfh);
        const char* w2 = reinterpret_cast<const char*>(g_W2h);
#pragma unroll
        for (int it = 0; it < 16; it++) {
            int idx = tid + it * 128;         // 2048 x 16B
            int r = idx >> 4, c = (idx & 15) << 3;
            uint32_t doff = (uint32_t)(r * PA + c) * 2;
            CP16(sb + OFF_B1 + doff, w1 + idx * 16);
            CP16(sb + OFF_B2 + doff, w2 + idx * 16);
        }
        CP_COMMIT();

        const float4* src = reinterpret_cast<const float4*>(
            pair_emb + ((size_t)blk * NDIM + j0) * HDIM);
#pragma unroll
        for (int it = 0; it < 32; it++) {
            int idx = tid + it * 128;         // 4096 float4
            float4 f = src[idx];
            int r = idx >> 5, c = (idx & 31) << 2;
            uint2 v; v.x = pack_h2(f.x, f.y); v.y = pack_h2(f.z, f.w);
            *reinterpret_cast<uint2*>(As + r * PA + c) = v;
        }
        if (tid < 128) {
            biasI[tid] = g_P[(size_t)blk * HDIM + tid] + g_b1eff[tid];
            w3s[tid] = W3[tid];
            b2s[tid] = b2[tid];
        }
        CP_WAIT0();
    }
    __syncthreads();

    float acc[4][8][4];

    // ---- GEMM1 ----
#pragma unroll
    for (int mt = 0; mt < 4; mt++)
#pragma unroll
        for (int nt = 0; nt < 8; nt++)
#pragma unroll
            for (int e = 0; e < 4; e++) acc[mt][nt][e] = 0.f;
    do_gemm(aLane, bLane1, acc);

    // wm-group barrier (2 warps): A-reads done before H1 overwrite
    BAR_GROUP(1 + wm);

    // ---- epilogue 1: silu(acc + biasI + Q[j]) -> H1 f16 into As ----
#pragma unroll
    for (int mt = 0; mt < 4; mt++) {
        int r = wm * 64 + mt * 16 + g;
        const __half* qrow = g_Qh + (size_t)(bbase + j0 + r) * HDIM;
#pragma unroll
        for (int nt = 0; nt < 8; nt++) {
            int c = wn * 64 + nt * 8 + l4 * 2;
            float2 ql = __half22float2(*reinterpret_cast<const __half2*>(qrow + c));
            float2 qh = __half22float2(*reinterpret_cast<const __half2*>(qrow + 8 * HDIM + c));
            float bc0 = biasI[c], bc1 = biasI[c + 1];
            float x0 = acc[mt][nt][0] + bc0 + ql.x;
            float x1 = acc[mt][nt][1] + bc1 + ql.y;
            float x2 = acc[mt][nt][2] + bc0 + qh.x;
            float x3 = acc[mt][nt][3] + bc1 + qh.y;
            *reinterpret_cast<unsigned*>(As + r * PA + c)       = silu2(x0, x1);
            *reinterpret_cast<unsigned*>(As + (r + 8) * PA + c) = silu2(x2, x3);
        }
    }
    BAR_GROUP(1 + wm);   // H1 column slices visible to both wn warps

    // ---- GEMM2 ----
#pragma unroll
    for (int mt = 0; mt < 4; mt++)
#pragma unroll
        for (int nt = 0; nt < 8; nt++)
#pragma unroll
            for (int e = 0; e < 4; e++) acc[mt][nt][e] = 0.f;
    do_gemm(aLane, bLane2, acc);

    // ---- epilogue 2: silu, dot W3, per-wn slice write ----
    float sAcc[4][2];
#pragma unroll
    for (int mt = 0; mt < 4; mt++) { sAcc[mt][0] = 0.f; sAcc[mt][1] = 0.f; }
#pragma unroll
    for (int mt = 0; mt < 4; mt++) {
#pragma unroll
        for (int nt = 0; nt < 8; nt++) {
            int c = wn * 64 + nt * 8 + l4 * 2;
            float bb0 = b2s[c], bb1 = b2s[c + 1];
            float w30 = w3s[c], w31 = w3s[c + 1];
            unsigned ylo = silu2(acc[mt][nt][0] + bb0, acc[mt][nt][1] + bb1);
            unsigned yhi = silu2(acc[mt][nt][2] + bb0, acc[mt][nt][3] + bb1);
            float2 y01 = __half22float2(*reinterpret_cast<__half2*>(&ylo));
            float2 y23 = __half22float2(*reinterpret_cast<__half2*>(&yhi));
            sAcc[mt][0] += y01.x * w30 + y01.y * w31;
            sAcc[mt][1] += y23.x * w30 + y23.y * w31;
        }
    }
#pragma unroll
    for (int mt = 0; mt < 4; mt++)
#pragma unroll
        for (int hh = 0; hh < 2; hh++) {
            sAcc[mt][hh] += __shfl_xor_sync(0xffffffffu, sAcc[mt][hh], 1);
            sAcc[mt][hh] += __shfl_xor_sync(0xffffffffu, sAcc[mt][hh], 2);
        }
    if (l4 == 0) {
#pragma unroll
        for (int mt = 0; mt < 4; mt++) {
            sRedW[wn * 128 + wm * 64 + mt * 16 + g]     = sAcc[mt][0];
            sRedW[wn * 128 + wm * 64 + mt * 16 + 8 + g] = sAcc[mt][1];
        }
    }
    BAR_GROUP(1 + wm);

    // ---- final: wn==0 warp of each wm reduces its 64 rows ----
    if (wn == 0) {
        float t0 = 0.f, t1 = 0.f, t2 = 0.f;
#pragma unroll
        for (int hh = 0; hh < 2; hh++) {
            int r = wm * 64 + hh * 32 + lane;
            size_t jj = (size_t)blk * NDIM + j0 + r;
            float s = sRedW[r] + sRedW[128 + r];
            float sj = s * pair_mask[jj];
            const float* cd = coord_diff + jj * 3;
            t0 = fmaf(cd[0], sj, t0);
            t1 = fmaf(cd[1], sj, t1);
            t2 = fmaf(cd[2], sj, t2);
        }
#pragma unroll
        for (int off = 16; off > 0; off >>= 1) {
            t0 += __shfl_down_sync(0xffffffffu, t0, off);
            t1 += __shfl_down_sync(0xffffffffu, t1, off);
            t2 += __shfl_down_sync(0xffffffffu, t2, off);
        }
        if (lane == 0) {
            float* gp = g_part + ((size_t)blk2 * 2 + wm) * 3;
            gp[0] = t0; gp[1] = t1; gp[2] = t2;
        }
    }
}

// ---------------- combine kernel ----------------
__global__ void combine(const float* __restrict__ pos, float* __restrict__ out) {
    int i = blockIdx.x * blockDim.x + threadIdx.x;   // 0..6143
    if (i < NODES * 3) {
        int node = i / 3, d = i - node * 3;
        const float* gp = g_part + (size_t)node * 4 * 3 + d;   // 2 halves x 2 wm
        out[i] = pos[i] + ((gp[0] + gp[3]) + (gp[6] + gp[9]));
    }
}

// ---------------- launcher ----------------
extern "C" void kernel_launch(void* const* d_in, const int* in_sizes, int n_in,
                              void* d_out, int out_size) {
    const float* x_emb      = (const float*)d_in[0];
    const float* pair_emb   = (const float*)d_in[1];
    const float* pos        = (const float*)d_in[2];
    const float* coord_diff = (const float*)d_in[3];
    const float* pair_mask  = (const float*)d_in[5];
    const float* Wd         = (const float*)d_in[6];
    const float* bd         = (const float*)d_in[7];
    const float* W1         = (const float*)d_in[8];
    const float* b1         = (const float*)d_in[9];
    const float* W2         = (const float*)d_in[10];
    const float* b2         = (const float*)d_in[11];
    const float* W3         = (const float*)d_in[12];
    float* out = (float*)d_out;

    cudaFuncSetAttribute(pos_update_main,
                         cudaFuncAttributeMaxDynamicSharedMemorySize, SMEM_TOTAL);

    prep_w<<<128, 256>>>(Wd, bd, W1, b1, W2);
    prep_pq<<<256, 256>>>(x_emb);
    pos_update_main<<<NTILES, 128, SMEM_TOTAL>>>(pair_emb, coord_diff,
                                                 pair_mask, b2, W3);
    combine<<<(NODES * 3 + 511) / 512, 512>>>(pos, out);
    (void)in_sizes; (void)n_in; (void)out_size;
}